// round 17
// baseline (speedup 1.0000x reference)
#include <cuda_runtime.h>
#include <cuda_bf16.h>
#include <mma.h>
#include <cstdint>

using namespace nvcuda;

#define T_DIM 512
#define B_DIM 512
#define I_DIM 100
#define H_DIM 96
#define G_DIM 288   // 3*H

// Scratch for input projections: [dir][t][b][3H]  (604 MB)
__device__ float g_xp[2][T_DIM][B_DIM][G_DIM];
// Pre-converted W_ih in bf16 hi/lo, K zero-padded to 128: [dir][hi/lo][g][k]
__device__ __nv_bfloat16 g_wbf[2][2][G_DIM][128];

// ---------------------------------------------------------------------------
// packed f32x2 ops (Blackwell)
// ---------------------------------------------------------------------------
__device__ __forceinline__ float2 ffma2(float2 a, float2 b, float2 c) {
    float2 d;
    asm("fma.rn.f32x2 %0, %1, %2, %3;"
        : "=l"(*reinterpret_cast<unsigned long long*>(&d))
        : "l"(*reinterpret_cast<unsigned long long*>(&a)),
          "l"(*reinterpret_cast<unsigned long long*>(&b)),
          "l"(*reinterpret_cast<unsigned long long*>(&c)));
    return d;
}
__device__ __forceinline__ float2 fadd2(float2 a, float2 b) {
    float2 d;
    asm("add.rn.f32x2 %0, %1, %2;"
        : "=l"(*reinterpret_cast<unsigned long long*>(&d))
        : "l"(*reinterpret_cast<unsigned long long*>(&a)),
          "l"(*reinterpret_cast<unsigned long long*>(&b)));
    return d;
}
__device__ __forceinline__ float sigmoidf_fast(float x) {
    return __fdividef(1.0f, 1.0f + __expf(-x));
}
__device__ __forceinline__ float tanhf_fast(float x) {
    return 2.0f * __fdividef(1.0f, 1.0f + __expf(-2.0f * x)) - 1.0f;
}

// ---------------------------------------------------------------------------
// Kernel 0: convert W_ih to bf16 hi/lo, zero-padded. grid 2, block 288.
// ---------------------------------------------------------------------------
__global__ void wconv_kernel(const float* __restrict__ w_f,
                             const float* __restrict__ w_b)
{
    const int dir = blockIdx.x;
    const float* __restrict__ W = dir ? w_b : w_f;
    const int g = threadIdx.x;
    for (int k = 0; k < 128; k++) {
        float v = (k < I_DIM) ? W[(size_t)g * I_DIM + k] : 0.0f;
        __nv_bfloat16 hi = __float2bfloat16_rn(v);
        __nv_bfloat16 lo = __float2bfloat16_rn(v - __bfloat162float(hi));
        g_wbf[dir][0][g][k] = hi;
        g_wbf[dir][1][g][k] = lo;
    }
}

// ---------------------------------------------------------------------------
// Kernel 1: projection GEMM on WMMA bf16 (split: hi*hi + hi*lo + lo*hi,
// fp32 accumulate). Persistent grid (74, dir=2), block 256 (8 warps: 4m x 2n).
// K padded to 112 (7 steps of 16). Per 64-row tile: convert x to hi/lo smem
// (double-buffered, fill-before-compute); each warp 16 rows x 144 cols =
// 9 acc frags initialized from a replicated bias tile; direct wmma store to
// g_xp. Smem: W hi/lo [112][296] x2 + A [2buf][2split][64][120] + bias[16][288]
// = 207.5 KB -> 1 CTA/SM.
// ---------------------------------------------------------------------------
#define WS_STRIDE 296   // halves; 592B rows (odd multiple of 16B: LDSM conflict-free)
#define AS_STRIDE 120   // halves; 240B rows (odd multiple of 16B)
#define KPAD 112
#define WS_BYTES  (KPAD * WS_STRIDE * 2)                  // 66304 per split
#define AS_BYTES  (64 * AS_STRIDE * 2)                    // 15360 per (buf,split)
#define OFF_WS_HI 0
#define OFF_WS_LO WS_BYTES
#define OFF_AS    (2 * WS_BYTES)                          // 132608
#define OFF_BIAS  (OFF_AS + 4 * AS_BYTES)                 // 194048
#define SMEM_PROJ (OFF_BIAS + 16 * G_DIM * 4)             // 212480 B

extern __shared__ char proj_sm[];

__global__ void __launch_bounds__(256, 1)
projmma_kernel(const float* __restrict__ x,
               const float* __restrict__ b_f, const float* __restrict__ b_b)
{
    const int dir = blockIdx.y;
    const int tid = threadIdx.x;
    const int wid = tid >> 5;
    const int wm  = wid & 3;    // m-tile: rows 16*wm .. +16 of the 64-row tile
    const int wn  = wid >> 2;   // n-half: cols 144*wn .. +144

    __nv_bfloat16* WsHi = reinterpret_cast<__nv_bfloat16*>(proj_sm + OFF_WS_HI);
    __nv_bfloat16* WsLo = reinterpret_cast<__nv_bfloat16*>(proj_sm + OFF_WS_LO);
    float* bias_s = reinterpret_cast<float*>(proj_sm + OFF_BIAS);
    auto As = [&](int buf, int p) -> __nv_bfloat16* {
        return reinterpret_cast<__nv_bfloat16*>(proj_sm + OFF_AS + (buf * 2 + p) * AS_BYTES);
    };

    // --- one-time fills ---
    // W transposed: Ws[k][g] = g_wbf[dir][p][g][k]  (k < 112; zeros beyond 100)
    for (int idx = tid; idx < 2 * KPAD * G_DIM; idx += 256) {
        int p   = idx / (KPAD * G_DIM);
        int rem = idx - p * KPAD * G_DIM;
        int k   = rem / G_DIM;
        int g   = rem - k * G_DIM;
        (p ? WsLo : WsHi)[k * WS_STRIDE + g] = g_wbf[dir][p][g][k];
    }
    // Bias tile: 16 identical rows
    {
        const float* __restrict__ bias = dir ? b_b : b_f;
        for (int idx = tid; idx < 16 * G_DIM; idx += 256)
            bias_s[idx] = bias[idx % G_DIM];
    }
    // Zero A pad columns k in [100,120) for all 4 (buf,split) buffers
    for (int idx = tid; idx < 4 * 64 * (AS_STRIDE - I_DIM); idx += 256) {
        int bp  = idx / (64 * (AS_STRIDE - I_DIM));
        int rem = idx - bp * 64 * (AS_STRIDE - I_DIM);
        int r   = rem / (AS_STRIDE - I_DIM);
        int k   = I_DIM + rem % (AS_STRIDE - I_DIM);
        As(bp >> 1, bp & 1)[r * AS_STRIDE + k] = __float2bfloat16_rn(0.0f);
    }

    float* __restrict__ xp_base = &g_xp[dir][0][0][0];
    const int ntiles = (T_DIM * B_DIM) / 64;   // 4096
    const int stride = gridDim.x;              // 74

    // Prologue: fill buffer 0
    {
        const size_t row0 = (size_t)blockIdx.x * 64;
        __nv_bfloat16* ah = As(0, 0);
        __nv_bfloat16* al = As(0, 1);
        for (int idx = tid; idx < 64 * I_DIM; idx += 256) {
            int r = idx / I_DIM;
            int k = idx - r * I_DIM;
            float v = x[(row0 + r) * I_DIM + k];
            __nv_bfloat16 hi = __float2bfloat16_rn(v);
            ah[r * AS_STRIDE + k] = hi;
            al[r * AS_STRIDE + k] = __float2bfloat16_rn(v - __bfloat162float(hi));
        }
    }
    __syncthreads();

    int buf = 0;
    for (int tile = blockIdx.x; tile < ntiles; tile += stride) {
        // Issue next tile's fill first (LDG latency overlaps MMA below)
        const int nxt = tile + stride;
        if (nxt < ntiles) {
            const size_t nrow0 = (size_t)nxt * 64;
            __nv_bfloat16* ah = As(buf ^ 1, 0);
            __nv_bfloat16* al = As(buf ^ 1, 1);
            for (int idx = tid; idx < 64 * I_DIM; idx += 256) {
                int r = idx / I_DIM;
                int k = idx - r * I_DIM;
                float v = x[(nrow0 + r) * I_DIM + k];
                __nv_bfloat16 hi = __float2bfloat16_rn(v);
                ah[r * AS_STRIDE + k] = hi;
                al[r * AS_STRIDE + k] = __float2bfloat16_rn(v - __bfloat162float(hi));
            }
        }

        // Compute: 9 n-tiles of 16, acc initialized from bias tile
        wmma::fragment<wmma::accumulator, 16, 16, 16, float> acc[9];
        #pragma unroll
        for (int n = 0; n < 9; n++)
            wmma::load_matrix_sync(acc[n], bias_s + wn * 144 + n * 16, G_DIM,
                                   wmma::mem_row_major);

        const __nv_bfloat16* ah = As(buf, 0) + 16 * wm * AS_STRIDE;
        const __nv_bfloat16* al = As(buf, 1) + 16 * wm * AS_STRIDE;

        #pragma unroll
        for (int ks = 0; ks < KPAD / 16; ks++) {
            const int k0 = ks * 16;
            wmma::fragment<wmma::matrix_a, 16, 16, 16, __nv_bfloat16, wmma::row_major> a_hi, a_lo;
            wmma::load_matrix_sync(a_hi, ah + k0, AS_STRIDE);
            wmma::load_matrix_sync(a_lo, al + k0, AS_STRIDE);
            #pragma unroll
            for (int n = 0; n < 9; n++) {
                const int col = wn * 144 + n * 16;
                wmma::fragment<wmma::matrix_b, 16, 16, 16, __nv_bfloat16, wmma::row_major> b_hi, b_lo;
                wmma::load_matrix_sync(b_hi, WsHi + k0 * WS_STRIDE + col, WS_STRIDE);
                wmma::load_matrix_sync(b_lo, WsLo + k0 * WS_STRIDE + col, WS_STRIDE);
                wmma::mma_sync(acc[n], a_hi, b_hi, acc[n]);
                wmma::mma_sync(acc[n], a_hi, b_lo, acc[n]);
                wmma::mma_sync(acc[n], a_lo, b_hi, acc[n]);
            }
        }

        // Store directly to g_xp
        {
            const size_t row0 = (size_t)tile * 64;
            float* __restrict__ op = xp_base + (row0 + 16 * wm) * G_DIM + wn * 144;
            #pragma unroll
            for (int n = 0; n < 9; n++)
                wmma::store_matrix_sync(op + n * 16, acc[n], G_DIM, wmma::mem_row_major);
        }

        __syncthreads();   // next-buffer fill complete; current-buffer reads done
        buf ^= 1;
    }
}

// ---------------------------------------------------------------------------
// Kernel 2: single-phase GRU scan — EXACT round-9/14 version (measured 910us).
// ---------------------------------------------------------------------------
#define R_PER_CTA 8
#define KPT 24

__global__ void __launch_bounds__(384, 1)
scan_kernel(const float* __restrict__ whh_f, const float* __restrict__ bhh_f,
            const float* __restrict__ whh_b, const float* __restrict__ bhh_b,
            float* __restrict__ out)
{
    __shared__ __align__(16) float h_s[2][H_DIM * R_PER_CTA];

    const int dir = blockIdx.y;
    const float* __restrict__ Whh = dir ? whh_b : whh_f;
    const float* __restrict__ bhh = dir ? bhh_b : bhh_f;
    const int tid = threadIdx.x;
    const int j   = tid >> 2;
    const int kq  = tid & 3;
    const int b0  = blockIdx.x * R_PER_CTA;
    const int r0  = 2 * kq;

    float wr[KPT], wz[KPT], wn[KPT];
    #pragma unroll
    for (int i = 0; i < KPT; i++) {
        int k = kq + 4 * i;
        wr[i] = Whh[(size_t)j * H_DIM + k];
        wz[i] = Whh[(size_t)(j + 96) * H_DIM + k];
        wn[i] = Whh[(size_t)(j + 192) * H_DIM + k];
    }
    const float br = (kq == 0) ? bhh[j]       : 0.0f;
    const float bz = (kq == 0) ? bhh[j + 96]  : 0.0f;
    const float bn = (kq == 0) ? bhh[j + 192] : 0.0f;

    for (int i = tid; i < 2 * H_DIM * R_PER_CTA; i += 384)
        (&h_s[0][0])[i] = 0.0f;
    float hold0 = 0.0f, hold1 = 0.0f;
    __syncthreads();

    const float* __restrict__ xp_dir = &g_xp[dir][0][0][0];

    for (int s = 0; s < T_DIM; s++) {
        const int t = dir ? (T_DIM - 1 - s) : s;

        const float* __restrict__ p0 =
            xp_dir + ((size_t)t * B_DIM + b0 + r0) * G_DIM + j;
        const float* __restrict__ p1 = p0 + G_DIM;
        float xr0 = p0[0], xz0 = p0[96], xn0 = p0[192];
        float xr1 = p1[0], xz1 = p1[96], xn1 = p1[192];

        const float* __restrict__ hb = h_s[s & 1];
        float2 ar0 = make_float2(br, br), ar1 = ar0, ar2 = ar0, ar3 = ar0;
        float2 az0 = make_float2(bz, bz), az1 = az0, az2 = az0, az3 = az0;
        float2 an0 = make_float2(bn, bn), an1 = an0, an2 = an0, an3 = an0;
        #pragma unroll
        for (int i = 0; i < KPT; i++) {
            int k = kq + 4 * i;
            float4 hA = *reinterpret_cast<const float4*>(&hb[k * 8]);
            float4 hB = *reinterpret_cast<const float4*>(&hb[k * 8 + 4]);
            float2 h01 = make_float2(hA.x, hA.y);
            float2 h23 = make_float2(hA.z, hA.w);
            float2 h45 = make_float2(hB.x, hB.y);
            float2 h67 = make_float2(hB.z, hB.w);
            float2 w2;
            w2 = make_float2(wr[i], wr[i]);
            ar0 = ffma2(h01, w2, ar0); ar1 = ffma2(h23, w2, ar1);
            ar2 = ffma2(h45, w2, ar2); ar3 = ffma2(h67, w2, ar3);
            w2 = make_float2(wz[i], wz[i]);
            az0 = ffma2(h01, w2, az0); az1 = ffma2(h23, w2, az1);
            az2 = ffma2(h45, w2, az2); az3 = ffma2(h67, w2, az3);
            w2 = make_float2(wn[i], wn[i]);
            an0 = ffma2(h01, w2, an0); an1 = ffma2(h23, w2, an1);
            an2 = ffma2(h45, w2, an2); an3 = ffma2(h67, w2, an3);
        }

        #define RED2(v, m)                                            \
            { float2 _o;                                              \
              _o.x = __shfl_xor_sync(0xFFFFFFFFu, (v).x, (m));        \
              _o.y = __shfl_xor_sync(0xFFFFFFFFu, (v).y, (m));        \
              (v) = fadd2((v), _o); }
        RED2(ar0, 1) RED2(ar1, 1) RED2(ar2, 1) RED2(ar3, 1)
        RED2(az0, 1) RED2(az1, 1) RED2(az2, 1) RED2(az3, 1)
        RED2(an0, 1) RED2(an1, 1) RED2(an2, 1) RED2(an3, 1)
        RED2(ar0, 2) RED2(ar1, 2) RED2(ar2, 2) RED2(ar3, 2)
        RED2(az0, 2) RED2(az1, 2) RED2(az2, 2) RED2(az3, 2)
        RED2(an0, 2) RED2(an1, 2) RED2(an2, 2) RED2(an3, 2)
        #undef RED2

        float2 vr = (kq & 2) ? ((kq & 1) ? ar3 : ar2) : ((kq & 1) ? ar1 : ar0);
        float2 vz = (kq & 2) ? ((kq & 1) ? az3 : az2) : ((kq & 1) ? az1 : az0);
        float2 vn = (kq & 2) ? ((kq & 1) ? an3 : an2) : ((kq & 1) ? an1 : an0);

        float rg0 = sigmoidf_fast(xr0 + vr.x);
        float zg0 = sigmoidf_fast(xz0 + vz.x);
        float ng0 = tanhf_fast(xn0 + rg0 * vn.x);
        float hn0 = ng0 + zg0 * (hold0 - ng0);
        float rg1 = sigmoidf_fast(xr1 + vr.y);
        float zg1 = sigmoidf_fast(xz1 + vz.y);
        float ng1 = tanhf_fast(xn1 + rg1 * vn.y);
        float hn1 = ng1 + zg1 * (hold1 - ng1);
        hold0 = hn0;
        hold1 = hn1;

        float* __restrict__ hw = h_s[(s + 1) & 1];
        *reinterpret_cast<float2*>(&hw[j * 8 + r0]) = make_float2(hn0, hn1);

        float* __restrict__ op =
            out + ((size_t)t * B_DIM + b0 + r0) * (2 * H_DIM) + dir * H_DIM + j;
        op[0]         = hn0;
        op[2 * H_DIM] = hn1;

        __syncthreads();
    }
}

// ---------------------------------------------------------------------------
extern "C" void kernel_launch(void* const* d_in, const int* in_sizes, int n_in,
                              void* d_out, int out_size)
{
    const float* x      = (const float*)d_in[0];
    const float* w_ih_f = (const float*)d_in[1];
    const float* w_hh_f = (const float*)d_in[2];
    const float* b_ih_f = (const float*)d_in[3];
    const float* b_hh_f = (const float*)d_in[4];
    const float* w_ih_b = (const float*)d_in[5];
    const float* w_hh_b = (const float*)d_in[6];
    const float* b_ih_b = (const float*)d_in[7];
    const float* b_hh_b = (const float*)d_in[8];
    float* out = (float*)d_out;

    cudaFuncSetAttribute(projmma_kernel,
                         cudaFuncAttributeMaxDynamicSharedMemorySize, SMEM_PROJ);

    wconv_kernel<<<2, 288>>>(w_ih_f, w_ih_b);
    projmma_kernel<<<dim3(74, 2), 256, SMEM_PROJ>>>(x, b_ih_f, b_ih_b);
    scan_kernel<<<dim3(B_DIM / R_PER_CTA, 2), 384>>>(w_hh_f, b_hh_f, w_hh_b, b_hh_b, out);
}